// round 6
// baseline (speedup 1.0000x reference)
#include <cuda_runtime.h>

// ConvCaps EM-routing: HALF-warp (16 lanes) per batch element, 2 elements/warp.
// lane = e*16 + hh2*8 + c. Weights batch-independent -> each weight LDS serves 2 elements.
// Slot s = k*4+u maps to input capsule B = 4*(hh2^k)+u (xor8 butterflies select-free).
// Algebra: sigma^2 = E[v^2]-mu^2 (fused single pass); Mahalanobis term expanded as
// v*(is*v - 2*mu*is) + const, with the const folded into the softmax bias.

#define FULLMASK 0xffffffffu
#define EPSF     1e-8f
#define HALF_LN2PI 0.9189385332046727f  // 0.5*ln(2*pi)

typedef unsigned long long u64;

__device__ __forceinline__ u64 pk2(float lo, float hi) {
    u64 r; asm("mov.b64 %0, {%1, %2};" : "=l"(r) : "f"(lo), "f"(hi)); return r;
}
__device__ __forceinline__ float2 up2(u64 v) {
    float2 f; asm("mov.b64 {%0, %1}, %2;" : "=f"(f.x), "=f"(f.y) : "l"(v)); return f;
}
__device__ __forceinline__ u64 ffma2(u64 a, u64 b, u64 c) {
    u64 d; asm("fma.rn.f32x2 %0, %1, %2, %3;" : "=l"(d) : "l"(a), "l"(b), "l"(c)); return d;
}
__device__ __forceinline__ u64 fadd2(u64 a, u64 b) {
    u64 d; asm("add.rn.f32x2 %0, %1, %2;" : "=l"(d) : "l"(a), "l"(b)); return d;
}
__device__ __forceinline__ u64 fmul2(u64 a, u64 b) {
    u64 d; asm("mul.rn.f32x2 %0, %1, %2;" : "=l"(d) : "l"(a), "l"(b)); return d;
}

static __global__ __launch_bounds__(256, 2)
void caps_kernel(const float* __restrict__ x,
                 const float* __restrict__ wts,
                 const float* __restrict__ bu_g,
                 const float* __restrict__ ba_g,
                 float* __restrict__ o1,   // p_out_p  [b][8][16]
                 float* __restrict__ o2,   // a_out_p  [b][8][1]
                 float* __restrict__ o3,   // out_p    [b][8][17]
                 float* __restrict__ o4,   // out      [b][136]
                 int batch)
{
    // weights transposed: w[B][c][k][j] -> w_s[(((B*4+k)*8+c)*4)+j]  (float4 per (B,k,c))
    __shared__ __align__(16) float w_s[1024];
    __shared__ float bu_s[8];
    __shared__ float ba_s[8];

    const int tid  = threadIdx.x;
    const int warp = tid >> 5;
    const int lane = tid & 31;
    const int e    = lane >> 4;
    const int c    = lane & 7;
    const int hh2  = (lane >> 3) & 1;

    #pragma unroll
    for (int t = 0; t < 4; ++t) {
        int ei = tid + t * 256;
        int B = ei >> 7, cc = (ei >> 4) & 7, k = (ei >> 2) & 3, j = ei & 3;
        w_s[((B * 4 + k) * 8 + cc) * 4 + j] = wts[ei];
    }
    if (tid < 8) { bu_s[tid] = bu_g[tid]; ba_s[tid] = ba_g[tid]; }

    long long b = (long long)blockIdx.x * 16 + warp * 2 + e;
    if (b >= (long long)batch) b = (long long)batch - 1;   // clamp: duplicate work, same stores
    const float* xg = x + b * 136;

    __syncthreads();

    // ---- activations: af = a/(a+eps)  (sum_C r == 1 identity). slot s=k*4+u -> B=4*(hh2^k)+u
    const float4 av0 = __ldg(reinterpret_cast<const float4*>(xg + 128)); // B 0..3
    const float4 av1 = __ldg(reinterpret_cast<const float4*>(xg + 132)); // B 4..7
    const float4 aown = hh2 ? av1 : av0;   // k=0 group
    const float4 aoth = hh2 ? av0 : av1;   // k=1 group
    float af[8];
    af[0] = aown.x * __fdividef(1.f, aown.x + EPSF);
    af[1] = aown.y * __fdividef(1.f, aown.y + EPSF);
    af[2] = aown.z * __fdividef(1.f, aown.z + EPSF);
    af[3] = aown.w * __fdividef(1.f, aown.w + EPSF);
    af[4] = aoth.x * __fdividef(1.f, aoth.x + EPSF);
    af[5] = aoth.y * __fdividef(1.f, aoth.y + EPSF);
    af[6] = aoth.z * __fdividef(1.f, aoth.z + EPSF);
    af[7] = aoth.w * __fdividef(1.f, aoth.w + EPSF);

    // ---- votes: lane owns pose rows i0=2*hh2, i0+1; 8 h values per slot.
    u64 vA01[8], vA23[8], vB01[8], vB23[8];
    const float4* w4 = reinterpret_cast<const float4*>(w_s);
    const int i0 = 2 * hh2;
    #pragma unroll
    for (int k = 0; k < 2; ++k) {
        const int g = hh2 ^ k;
        #pragma unroll
        for (int u = 0; u < 4; ++u) {
            const int B = 4 * g + u;
            const int s = k * 4 + u;
            const float4 pA = __ldg(reinterpret_cast<const float4*>(xg + B * 16 + i0 * 4));
            const float4 pB = __ldg(reinterpret_cast<const float4*>(xg + B * 16 + i0 * 4 + 4));
            const float4* wB = w4 + B * 32 + c;
            const float4 w0 = wB[0];
            const float4 w1 = wB[8];
            const float4 w2 = wB[16];
            const float4 w3 = wB[24];
            const u64 wk0a = pk2(w0.x, w0.y), wk0b = pk2(w0.z, w0.w);
            const u64 wk1a = pk2(w1.x, w1.y), wk1b = pk2(w1.z, w1.w);
            const u64 wk2a = pk2(w2.x, w2.y), wk2b = pk2(w2.z, w2.w);
            const u64 wk3a = pk2(w3.x, w3.y), wk3b = pk2(w3.z, w3.w);

            u64 q0 = pk2(pA.x, pA.x), q1 = pk2(pA.y, pA.y);
            u64 q2 = pk2(pA.z, pA.z), q3 = pk2(pA.w, pA.w);
            u64 r01 = fmul2(q0, wk0a);
            r01 = ffma2(q1, wk1a, r01);
            r01 = ffma2(q2, wk2a, r01);
            r01 = ffma2(q3, wk3a, r01);
            u64 r23 = fmul2(q0, wk0b);
            r23 = ffma2(q1, wk1b, r23);
            r23 = ffma2(q2, wk2b, r23);
            r23 = ffma2(q3, wk3b, r23);
            vA01[s] = r01; vA23[s] = r23;

            q0 = pk2(pB.x, pB.x); q1 = pk2(pB.y, pB.y);
            q2 = pk2(pB.z, pB.z); q3 = pk2(pB.w, pB.w);
            r01 = fmul2(q0, wk0a);
            r01 = ffma2(q1, wk1a, r01);
            r01 = ffma2(q2, wk2a, r01);
            r01 = ffma2(q3, wk3a, r01);
            r23 = fmul2(q0, wk0b);
            r23 = ffma2(q1, wk1b, r23);
            r23 = ffma2(q2, wk2b, r23);
            r23 = ffma2(q3, wk3b, r23);
            vB01[s] = r01; vB23[s] = r23;
        }
    }

    const float bu = bu_s[c];
    const float ba = ba_s[c];
    const u64 NEG1 = pk2(-1.f, -1.f);
    const u64 M2   = pk2(-2.f, -2.f);

    float rrn[8];
    #pragma unroll
    for (int s = 0; s < 8; ++s) rrn[s] = 0.125f * af[s];

    u64 muA01 = 0, muA23 = 0, muB01 = 0, muB23 = 0;
    float a_out = 0.f;

    #pragma unroll
    for (int it = 0; it < 3; ++it) {
        float r_sum = 0.f;
        #pragma unroll
        for (int s = 0; s < 8; ++s) r_sum += rrn[s];

        const float invrs = __fdividef(1.f, r_sum + EPSF);
        const u64 iv2 = pk2(invrs, invrs);

        // fused: m = sum rrn*v ; q = sum rrn*v^2
        u64 mA01 = 0, mA23 = 0, mB01 = 0, mB23 = 0;
        u64 qA01 = 0, qA23 = 0, qB01 = 0, qB23 = 0;
        #pragma unroll
        for (int s = 0; s < 8; ++s) {
            const u64 cb = pk2(rrn[s], rrn[s]);
            mA01 = ffma2(cb, vA01[s], mA01); qA01 = ffma2(cb, fmul2(vA01[s], vA01[s]), qA01);
            mA23 = ffma2(cb, vA23[s], mA23); qA23 = ffma2(cb, fmul2(vA23[s], vA23[s]), qA23);
            mB01 = ffma2(cb, vB01[s], mB01); qB01 = ffma2(cb, fmul2(vB01[s], vB01[s]), qB01);
            mB23 = ffma2(cb, vB23[s], mB23); qB23 = ffma2(cb, fmul2(vB23[s], vB23[s]), qB23);
        }
        muA01 = fmul2(mA01, iv2);
        muA23 = fmul2(mA23, iv2);
        muB01 = fmul2(mB01, iv2);
        muB23 = fmul2(mB23, iv2);

        // sigma^2 = E[v^2] - mu^2 (clamped) + eps
        const u64 sgA01 = ffma2(fmul2(muA01, NEG1), muA01, fmul2(qA01, iv2));
        const u64 sgA23 = ffma2(fmul2(muA23, NEG1), muA23, fmul2(qA23, iv2));
        const u64 sgB01 = ffma2(fmul2(muB01, NEG1), muB01, fmul2(qB01, iv2));
        const u64 sgB23 = ffma2(fmul2(muB23, NEG1), muB23, fmul2(qB23, iv2));
        float2 fA0 = up2(sgA01), fA2 = up2(sgA23);
        float2 fB0 = up2(sgB01), fB2 = up2(sgB23);
        fA0.x = fmaxf(fA0.x, 0.f) + EPSF; fA0.y = fmaxf(fA0.y, 0.f) + EPSF;
        fA2.x = fmaxf(fA2.x, 0.f) + EPSF; fA2.y = fmaxf(fA2.y, 0.f) + EPSF;
        fB0.x = fmaxf(fB0.x, 0.f) + EPSF; fB0.y = fmaxf(fB0.y, 0.f) + EPSF;
        fB2.x = fmaxf(fB2.x, 0.f) + EPSF; fB2.y = fmaxf(fB2.y, 0.f) + EPSF;

        // pairwise-merged logs
        const float lp0 = __logf(fA0.x * fA0.y);
        const float lp1 = __logf(fA2.x * fA2.y);
        const float lp2 = __logf(fB0.x * fB0.y);
        const float lp3 = __logf(fB2.x * fB2.y);
        float hpart = 0.5f * ((lp0 + lp1) + (lp2 + lp3));
        float Hs = hpart + __shfl_xor_sync(FULLMASK, hpart, 8);

        const float cost = r_sum * (16.f * bu + Hs);
        const float z  = 1e-3f * (ba - cost);
        const float ez = __expf(-z);
        a_out = __fdividef(1.f, 1.f + ez);

        if (it < 2) {
            const float la = -__logf(1.f + ez);          // log(sigmoid(z))
            // is = 1/sig; mis = mu*is; m2 = -2*mis; K2 = sum_h mu^2*is (own 8 h)
            const u64 iA01 = pk2(__fdividef(1.f, fA0.x), __fdividef(1.f, fA0.y));
            const u64 iA23 = pk2(__fdividef(1.f, fA2.x), __fdividef(1.f, fA2.y));
            const u64 iB01 = pk2(__fdividef(1.f, fB0.x), __fdividef(1.f, fB0.y));
            const u64 iB23 = pk2(__fdividef(1.f, fB2.x), __fdividef(1.f, fB2.y));
            const u64 misA01 = fmul2(muA01, iA01), misA23 = fmul2(muA23, iA23);
            const u64 misB01 = fmul2(muB01, iB01), misB23 = fmul2(muB23, iB23);
            const u64 m2A01 = fmul2(misA01, M2), m2A23 = fmul2(misA23, M2);
            const u64 m2B01 = fmul2(misB01, M2), m2B23 = fmul2(misB23, M2);
            u64 k2p = fmul2(muA01, misA01);
            k2p = ffma2(muA23, misA23, k2p);
            k2p = ffma2(muB01, misB01, k2p);
            k2p = ffma2(muB23, misB23, k2p);
            const float2 k2u = up2(k2p);
            const float K2h = 0.5f * (k2u.x + k2u.y);
            // fold both halves' K2 into the softmax bias
            const float Kc = la - Hs - 16.f * HALF_LN2PI
                           - (K2h + __shfl_xor_sync(FULLMASK, K2h, 8));

            // tp[s] = 0.5 * sum_own_h v*(is*v - 2*mu*is)
            float tp[8];
            #pragma unroll
            for (int s = 0; s < 8; ++s) {
                u64 t2, w;
                w  = ffma2(iA01, vA01[s], m2A01); t2 = fmul2(vA01[s], w);
                w  = ffma2(iA23, vA23[s], m2A23); t2 = ffma2(vA23[s], w, t2);
                w  = ffma2(iB01, vB01[s], m2B01); t2 = ffma2(vB01[s], w, t2);
                w  = ffma2(iB23, vB23[s], m2B23); t2 = ffma2(vB23[s], w, t2);
                const float2 tu = up2(t2);
                tp[s] = 0.5f * (tu.x + tu.y);
            }

            // reduce-scatter over hh2 (xor8)
            float tf[4];
            #pragma unroll
            for (int u = 0; u < 4; ++u)
                tf[u] = tp[u] + __shfl_xor_sync(FULLMASK, tp[4 + u], 8);

            // softmax over C for this group's 4 B's
            float rloc[4];
            #pragma unroll
            for (int u = 0; u < 4; ++u) {
                const float ln = Kc - tf[u];
                float m = ln;
                m = fmaxf(m, __shfl_xor_sync(FULLMASK, m, 1));
                m = fmaxf(m, __shfl_xor_sync(FULLMASK, m, 2));
                m = fmaxf(m, __shfl_xor_sync(FULLMASK, m, 4));
                const float ex = __expf(ln - m);
                float ssum = ex;
                ssum += __shfl_xor_sync(FULLMASK, ssum, 1);
                ssum += __shfl_xor_sync(FULLMASK, ssum, 2);
                ssum += __shfl_xor_sync(FULLMASK, ssum, 4);
                rloc[u] = ex * __fdividef(1.f, ssum);
            }

            // all-gather other group's r (xor8)
            #pragma unroll
            for (int u = 0; u < 4; ++u) {
                rrn[u]     = rloc[u] * af[u];
                rrn[4 + u] = __shfl_xor_sync(FULLMASK, rloc[u], 8) * af[4 + u];
            }
        }
    }

    const float2 mA0 = up2(muA01), mA2 = up2(muA23);
    const float2 mB0 = up2(muB01), mB2 = up2(muB23);
    const float4 m4A = make_float4(mA0.x, mA0.y, mA2.x, mA2.y);   // row i0
    const float4 m4B = make_float4(mB0.x, mB0.y, mB2.x, mB2.y);   // row i0+1

    if (o1) {   // p_out_p [b][c][16]
        *reinterpret_cast<float4*>(o1 + b * 128 + c * 16 + i0 * 4)     = m4A;
        *reinterpret_cast<float4*>(o1 + b * 128 + c * 16 + i0 * 4 + 4) = m4B;
    }
    if (o2 && hh2 == 0) {   // a_out_p [b][c]
        o2[b * 8 + c] = a_out;
    }
    if (o3) {   // out_p [b][c][17]
        float* p = o3 + b * 136 + c * 17 + i0 * 4;
        p[0] = m4A.x; p[1] = m4A.y; p[2] = m4A.z; p[3] = m4A.w;
        p[4] = m4B.x; p[5] = m4B.y; p[6] = m4B.z; p[7] = m4B.w;
        if (hh2 == 0) o3[b * 136 + c * 17 + 16] = a_out;
    }
    if (o4) {   // out [b][136] : 128 mu then 8 a_out
        *reinterpret_cast<float4*>(o4 + b * 136 + c * 16 + i0 * 4)     = m4A;
        *reinterpret_cast<float4*>(o4 + b * 136 + c * 16 + i0 * 4 + 4) = m4B;
        if (hh2 == 0) o4[b * 136 + 128 + c] = a_out;
    }
}

extern "C" void kernel_launch(void* const* d_in, const int* in_sizes, int n_in,
                              void* d_out, int out_size)
{
    const float* x  = (const float*)d_in[0];
    const float* w  = (const float*)d_in[1];
    const float* bu = (const float*)d_in[2];
    const float* ba = (const float*)d_in[3];
    float* out = (float*)d_out;

    const int batch = in_sizes[0] / 136;

    float *o1 = nullptr, *o2 = nullptr, *o3 = nullptr, *o4 = nullptr;
    if ((long long)out_size == (long long)batch * 136) {
        o4 = out;
    } else {
        o1 = out;
        o2 = o1 + (long long)batch * 128;
        o3 = o2 + (long long)batch * 8;
        o4 = o3 + (long long)batch * 136;
    }

    const int grid = (batch + 15) / 16;
    caps_kernel<<<grid, 256>>>(x, w, bu, ba, o1, o2, o3, o4, batch);
}

// round 7
// speedup vs baseline: 1.1960x; 1.1960x over previous
#include <cuda_runtime.h>

// ConvCaps EM-routing: HALF-warp (16 lanes) per batch element, 2 elements/warp.
// lane = e*16 + hh2*8 + c  (e = element half, hh2 in {0,1} owns pose rows 2*hh2, 2*hh2+1,
// c = output capsule). Weights are batch-independent -> each weight LDS serves 2 elements.
// Per-B state in RELATIVE slot order: slot s = k*4+u, input capsule B = 4*(hh2^k)+u, so
// xor8 butterflies are select-free. Softmax over C via xor{1,2,4} within c-octets.
// (R6's E[v^2]-mu^2 algebra reverted: catastrophic cancellation + register spills.)

#define FULLMASK 0xffffffffu
#define EPSF     1e-8f
#define HALF_LN2PI 0.9189385332046727f  // 0.5*ln(2*pi)

typedef unsigned long long u64;

__device__ __forceinline__ u64 pk2(float lo, float hi) {
    u64 r; asm("mov.b64 %0, {%1, %2};" : "=l"(r) : "f"(lo), "f"(hi)); return r;
}
__device__ __forceinline__ float2 up2(u64 v) {
    float2 f; asm("mov.b64 {%0, %1}, %2;" : "=f"(f.x), "=f"(f.y) : "l"(v)); return f;
}
__device__ __forceinline__ u64 ffma2(u64 a, u64 b, u64 c) {
    u64 d; asm("fma.rn.f32x2 %0, %1, %2, %3;" : "=l"(d) : "l"(a), "l"(b), "l"(c)); return d;
}
__device__ __forceinline__ u64 fadd2(u64 a, u64 b) {
    u64 d; asm("add.rn.f32x2 %0, %1, %2;" : "=l"(d) : "l"(a), "l"(b)); return d;
}
__device__ __forceinline__ u64 fmul2(u64 a, u64 b) {
    u64 d; asm("mul.rn.f32x2 %0, %1, %2;" : "=l"(d) : "l"(a), "l"(b)); return d;
}

static __global__ __launch_bounds__(256, 2)
void caps_kernel(const float* __restrict__ x,
                 const float* __restrict__ wts,
                 const float* __restrict__ bu_g,
                 const float* __restrict__ ba_g,
                 float* __restrict__ o1,   // p_out_p  [b][8][16]
                 float* __restrict__ o2,   // a_out_p  [b][8][1]
                 float* __restrict__ o3,   // out_p    [b][8][17]
                 float* __restrict__ o4,   // out      [b][136]
                 int batch)
{
    // weights transposed: w[B][c][k][j] -> w_s[(((B*4+k)*8+c)*4)+j]  (float4 per (B,k,c))
    __shared__ __align__(16) float w_s[1024];
    __shared__ float bu_s[8];
    __shared__ float ba_s[8];

    const int tid  = threadIdx.x;
    const int warp = tid >> 5;
    const int lane = tid & 31;
    const int e    = lane >> 4;
    const int c    = lane & 7;
    const int hh2  = (lane >> 3) & 1;

    #pragma unroll
    for (int t = 0; t < 4; ++t) {
        int ei = tid + t * 256;
        int B = ei >> 7, cc = (ei >> 4) & 7, k = (ei >> 2) & 3, j = ei & 3;
        w_s[((B * 4 + k) * 8 + cc) * 4 + j] = wts[ei];
    }
    if (tid < 8) { bu_s[tid] = bu_g[tid]; ba_s[tid] = ba_g[tid]; }

    long long b = (long long)blockIdx.x * 16 + warp * 2 + e;
    if (b >= (long long)batch) b = (long long)batch - 1;   // clamp: duplicate work, same stores
    const float* xg = x + b * 136;

    // ---- activations (issued BEFORE the barrier to overlap cold-load latency)
    const float4 av0 = __ldg(reinterpret_cast<const float4*>(xg + 128)); // B 0..3
    const float4 av1 = __ldg(reinterpret_cast<const float4*>(xg + 132)); // B 4..7
    const float4 aown = hh2 ? av1 : av0;   // k=0 group
    const float4 aoth = hh2 ? av0 : av1;   // k=1 group
    float af[8];   // af = a/(a+eps)  (sum_C r == 1 identity). slot s=k*4+u -> B=4*(hh2^k)+u
    af[0] = aown.x * __fdividef(1.f, aown.x + EPSF);
    af[1] = aown.y * __fdividef(1.f, aown.y + EPSF);
    af[2] = aown.z * __fdividef(1.f, aown.z + EPSF);
    af[3] = aown.w * __fdividef(1.f, aown.w + EPSF);
    af[4] = aoth.x * __fdividef(1.f, aoth.x + EPSF);
    af[5] = aoth.y * __fdividef(1.f, aoth.y + EPSF);
    af[6] = aoth.z * __fdividef(1.f, aoth.z + EPSF);
    af[7] = aoth.w * __fdividef(1.f, aoth.w + EPSF);

    __syncthreads();

    // ---- votes: lane owns pose rows i0=2*hh2, i0+1; 8 h values per slot.
    // vA* = row i0, vB* = row i1; *01 = (j0,j1), *23 = (j2,j3)
    u64 vA01[8], vA23[8], vB01[8], vB23[8];
    const float4* w4 = reinterpret_cast<const float4*>(w_s);
    const int i0 = 2 * hh2;
    #pragma unroll
    for (int k = 0; k < 2; ++k) {
        const int g = hh2 ^ k;
        #pragma unroll
        for (int u = 0; u < 4; ++u) {
            const int B = 4 * g + u;
            const int s = k * 4 + u;
            const float4 pA = __ldg(reinterpret_cast<const float4*>(xg + B * 16 + i0 * 4));
            const float4 pB = __ldg(reinterpret_cast<const float4*>(xg + B * 16 + i0 * 4 + 4));
            const float4* wB = w4 + B * 32 + c;
            const float4 w0 = wB[0];
            const float4 w1 = wB[8];
            const float4 w2 = wB[16];
            const float4 w3 = wB[24];
            const u64 wk0a = pk2(w0.x, w0.y), wk0b = pk2(w0.z, w0.w);
            const u64 wk1a = pk2(w1.x, w1.y), wk1b = pk2(w1.z, w1.w);
            const u64 wk2a = pk2(w2.x, w2.y), wk2b = pk2(w2.z, w2.w);
            const u64 wk3a = pk2(w3.x, w3.y), wk3b = pk2(w3.z, w3.w);

            u64 q0 = pk2(pA.x, pA.x), q1 = pk2(pA.y, pA.y);
            u64 q2 = pk2(pA.z, pA.z), q3 = pk2(pA.w, pA.w);
            u64 r01 = fmul2(q0, wk0a);
            r01 = ffma2(q1, wk1a, r01);
            r01 = ffma2(q2, wk2a, r01);
            r01 = ffma2(q3, wk3a, r01);
            u64 r23 = fmul2(q0, wk0b);
            r23 = ffma2(q1, wk1b, r23);
            r23 = ffma2(q2, wk2b, r23);
            r23 = ffma2(q3, wk3b, r23);
            vA01[s] = r01; vA23[s] = r23;

            q0 = pk2(pB.x, pB.x); q1 = pk2(pB.y, pB.y);
            q2 = pk2(pB.z, pB.z); q3 = pk2(pB.w, pB.w);
            r01 = fmul2(q0, wk0a);
            r01 = ffma2(q1, wk1a, r01);
            r01 = ffma2(q2, wk2a, r01);
            r01 = ffma2(q3, wk3a, r01);
            r23 = fmul2(q0, wk0b);
            r23 = ffma2(q1, wk1b, r23);
            r23 = ffma2(q2, wk2b, r23);
            r23 = ffma2(q3, wk3b, r23);
            vB01[s] = r01; vB23[s] = r23;
        }
    }

    const float bu = bu_s[c];
    const float ba = ba_s[c];
    const u64 NEG1 = pk2(-1.f, -1.f);
    const u64 EPS2 = pk2(EPSF, EPSF);

    float rrn[8];
    #pragma unroll
    for (int s = 0; s < 8; ++s) rrn[s] = 0.125f * af[s];

    u64 muA01 = 0, muA23 = 0, muB01 = 0, muB23 = 0;
    float a_out = 0.f;

    #pragma unroll
    for (int it = 0; it < 3; ++it) {
        float r_sum = 0.f;
        #pragma unroll
        for (int s = 0; s < 8; ++s) r_sum += rrn[s];

        const float invrs = __fdividef(1.f, r_sum + EPSF);
        const u64 iv2 = pk2(invrs, invrs);

        // mu = invrs * sum rrn*v
        u64 mA01 = 0, mA23 = 0, mB01 = 0, mB23 = 0;
        #pragma unroll
        for (int s = 0; s < 8; ++s) {
            const u64 cb = pk2(rrn[s], rrn[s]);
            mA01 = ffma2(cb, vA01[s], mA01);
            mA23 = ffma2(cb, vA23[s], mA23);
            mB01 = ffma2(cb, vB01[s], mB01);
            mB23 = ffma2(cb, vB23[s], mB23);
        }
        muA01 = fmul2(mA01, iv2);
        muA23 = fmul2(mA23, iv2);
        muB01 = fmul2(mB01, iv2);
        muB23 = fmul2(mB23, iv2);

        // sigma^2 = invrs * sum rrn*(v-mu)^2 + eps   (numerically-stable form)
        const u64 nA01 = fmul2(muA01, NEG1), nA23 = fmul2(muA23, NEG1);
        const u64 nB01 = fmul2(muB01, NEG1), nB23 = fmul2(muB23, NEG1);
        u64 sA01 = 0, sA23 = 0, sB01 = 0, sB23 = 0;
        #pragma unroll
        for (int s = 0; s < 8; ++s) {
            const u64 cb = pk2(rrn[s], rrn[s]);
            u64 d;
            d = fadd2(vA01[s], nA01); sA01 = ffma2(fmul2(cb, d), d, sA01);
            d = fadd2(vA23[s], nA23); sA23 = ffma2(fmul2(cb, d), d, sA23);
            d = fadd2(vB01[s], nB01); sB01 = ffma2(fmul2(cb, d), d, sB01);
            d = fadd2(vB23[s], nB23); sB23 = ffma2(fmul2(cb, d), d, sB23);
        }
        const u64 gA01 = ffma2(sA01, iv2, EPS2);
        const u64 gA23 = ffma2(sA23, iv2, EPS2);
        const u64 gB01 = ffma2(sB01, iv2, EPS2);
        const u64 gB23 = ffma2(sB23, iv2, EPS2);
        const float2 fA0 = up2(gA01), fA2 = up2(gA23);
        const float2 fB0 = up2(gB01), fB2 = up2(gB23);

        // pairwise-merged logs: sum_h log(sig) via 4 pair logs (pair prod >= 1e-16, safe)
        const float lp0 = __logf(fA0.x * fA0.y);
        const float lp1 = __logf(fA2.x * fA2.y);
        const float lp2 = __logf(fB0.x * fB0.y);
        const float lp3 = __logf(fB2.x * fB2.y);
        float hpart = 0.5f * ((lp0 + lp1) + (lp2 + lp3));
        float Hs = hpart + __shfl_xor_sync(FULLMASK, hpart, 8);

        const float cost = r_sum * (16.f * bu + Hs);
        const float z  = 1e-3f * (ba - cost);
        const float ez = __expf(-z);

        if (it == 2) {
            a_out = __fdividef(1.f, 1.f + ez);       // only the final a_out is an output
        } else {
            const float la = -__logf(1.f + ez);      // log(sigmoid(z))
            const float Kc = la - Hs - 16.f * HALF_LN2PI;
            // is = 1/sig (0.5 factor folded into tp scale)
            const u64 iA01 = pk2(__fdividef(1.f, fA0.x), __fdividef(1.f, fA0.y));
            const u64 iA23 = pk2(__fdividef(1.f, fA2.x), __fdividef(1.f, fA2.y));
            const u64 iB01 = pk2(__fdividef(1.f, fB0.x), __fdividef(1.f, fB0.y));
            const u64 iB23 = pk2(__fdividef(1.f, fB2.x), __fdividef(1.f, fB2.y));

            float tp[8];
            #pragma unroll
            for (int s = 0; s < 8; ++s) {
                u64 d, t2;
                d = fadd2(vA01[s], nA01); t2 = fmul2(fmul2(d, iA01), d);
                d = fadd2(vA23[s], nA23); t2 = ffma2(fmul2(d, iA23), d, t2);
                d = fadd2(vB01[s], nB01); t2 = ffma2(fmul2(d, iB01), d, t2);
                d = fadd2(vB23[s], nB23); t2 = ffma2(fmul2(d, iB23), d, t2);
                const float2 tu = up2(t2);
                tp[s] = 0.5f * (tu.x + tu.y);
            }

            // reduce-scatter over hh2 (xor8): own group's 4 B's
            float tf[4];
            #pragma unroll
            for (int u = 0; u < 4; ++u)
                tf[u] = tp[u] + __shfl_xor_sync(FULLMASK, tp[4 + u], 8);

            // softmax over C for this group's 4 B's
            float rloc[4];
            #pragma unroll
            for (int u = 0; u < 4; ++u) {
                const float ln = Kc - tf[u];
                float m = ln;
                m = fmaxf(m, __shfl_xor_sync(FULLMASK, m, 1));
                m = fmaxf(m, __shfl_xor_sync(FULLMASK, m, 2));
                m = fmaxf(m, __shfl_xor_sync(FULLMASK, m, 4));
                const float ex = __expf(ln - m);
                float ssum = ex;
                ssum += __shfl_xor_sync(FULLMASK, ssum, 1);
                ssum += __shfl_xor_sync(FULLMASK, ssum, 2);
                ssum += __shfl_xor_sync(FULLMASK, ssum, 4);
                rloc[u] = ex * __fdividef(1.f, ssum);
            }

            // all-gather other group's r (xor8)
            #pragma unroll
            for (int u = 0; u < 4; ++u) {
                rrn[u]     = rloc[u] * af[u];
                rrn[4 + u] = __shfl_xor_sync(FULLMASK, rloc[u], 8) * af[4 + u];
            }
        }
    }

    const float2 mA0 = up2(muA01), mA2 = up2(muA23);
    const float2 mB0 = up2(muB01), mB2 = up2(muB23);
    const float4 m4A = make_float4(mA0.x, mA0.y, mA2.x, mA2.y);   // row i0
    const float4 m4B = make_float4(mB0.x, mB0.y, mB2.x, mB2.y);   // row i0+1

    if (o1) {   // p_out_p [b][c][16]
        *reinterpret_cast<float4*>(o1 + b * 128 + c * 16 + i0 * 4)     = m4A;
        *reinterpret_cast<float4*>(o1 + b * 128 + c * 16 + i0 * 4 + 4) = m4B;
    }
    if (o2 && hh2 == 0) {   // a_out_p [b][c]
        o2[b * 8 + c] = a_out;
    }
    if (o3) {   // out_p [b][c][17]
        float* p = o3 + b * 136 + c * 17 + i0 * 4;
        p[0] = m4A.x; p[1] = m4A.y; p[2] = m4A.z; p[3] = m4A.w;
        p[4] = m4B.x; p[5] = m4B.y; p[6] = m4B.z; p[7] = m4B.w;
        if (hh2 == 0) o3[b * 136 + c * 17 + 16] = a_out;
    }
    if (o4) {   // out [b][136] : 128 mu then 8 a_out
        *reinterpret_cast<float4*>(o4 + b * 136 + c * 16 + i0 * 4)     = m4A;
        *reinterpret_cast<float4*>(o4 + b * 136 + c * 16 + i0 * 4 + 4) = m4B;
        if (hh2 == 0) o4[b * 136 + 128 + c] = a_out;
    }
}

extern "C" void kernel_launch(void* const* d_in, const int* in_sizes, int n_in,
                              void* d_out, int out_size)
{
    const float* x  = (const float*)d_in[0];
    const float* w  = (const float*)d_in[1];
    const float* bu = (const float*)d_in[2];
    const float* ba = (const float*)d_in[3];
    float* out = (float*)d_out;

    const int batch = in_sizes[0] / 136;

    float *o1 = nullptr, *o2 = nullptr, *o3 = nullptr, *o4 = nullptr;
    if ((long long)out_size == (long long)batch * 136) {
        o4 = out;
    } else {
        o1 = out;
        o2 = o1 + (long long)batch * 128;
        o3 = o2 + (long long)batch * 8;
        o4 = o3 + (long long)batch * 136;
    }

    const int grid = (batch + 15) / 16;
    caps_kernel<<<grid, 256>>>(x, w, bu, ba, o1, o2, o3, o4, batch);
}